// round 2
// baseline (speedup 1.0000x reference)
#include <cuda_runtime.h>
#include <cuda_bf16.h>

// ITLRegularizer: r = log(sqrt(mxx*mzz+1e-5)/(mxz+1e-5)) * theta
// where m** are means of exp(-d2/ks)/sqrt(2*pi*ks) over 8192x8192 pairs, D=3.
//
// Factored form: exp(-(|xi|^2+|qj|^2-2 xi.qj)/ks) = b_i * b_j * exp2(s * xi.qj)
// with b = exp2(-L*|p|^2/ks), s = 2L/ks, L = log2(e).

#define CAP 8192
#define MAXBLOCKS 4096

__device__ float4 g_px[CAP];
__device__ float4 g_pz[CAP];
__device__ float  g_partial[MAXBLOCKS * 3];

__device__ __forceinline__ float ex2(float a) {
    float r;
    asm("ex2.approx.ftz.f32 %0, %1;" : "=f"(r) : "f"(a));
    return r;
}

__global__ void itl_prep(const float* __restrict__ x,
                         const float* __restrict__ z,
                         const float* __restrict__ ksp, int N) {
    int i = blockIdx.x * blockDim.x + threadIdx.x;
    if (i >= N) return;
    const float L = 1.4426950408889634f;
    float inv_ks = 1.0f / ksp[0];
    float c = -L * inv_ks;

    float x0 = x[3 * i], x1 = x[3 * i + 1], x2 = x[3 * i + 2];
    float xb = ex2(c * (x0 * x0 + x1 * x1 + x2 * x2));
    g_px[i] = make_float4(x0, x1, x2, xb);

    float z0 = z[3 * i], z1 = z[3 * i + 1], z2 = z[3 * i + 2];
    float zb = ex2(c * (z0 * z0 + z1 * z1 + z2 * z2));
    g_pz[i] = make_float4(z0, z1, z2, zb);
}

__global__ void __launch_bounds__(256) itl_pairs(const float* __restrict__ ksp,
                                                 int N, int JS) {
    const float L = 1.4426950408889634f;
    float s = 2.0f * L / ksp[0];

    int i = blockIdx.x * blockDim.x + threadIdx.x;
    int jc = blockIdx.y;
    int j0 = (int)((long long)jc * N / JS);
    int j1 = (int)((long long)(jc + 1) * N / JS);

    float sxx = 0.0f, szz = 0.0f, sxz = 0.0f;

    if (i < N) {
        float4 pi = g_px[i];
        float4 qi = g_pz[i];
        float xi0 = pi.x * s, xi1 = pi.y * s, xi2 = pi.z * s;
        float zi0 = qi.x * s, zi1 = qi.y * s, zi2 = qi.z * s;

        #pragma unroll 4
        for (int j = j0; j < j1; j++) {
            float4 pj = g_px[j];
            float4 qj = g_pz[j];
            // XX term: x_i vs x_j
            float ax = fmaf(xi2, pj.z, fmaf(xi1, pj.y, xi0 * pj.x));
            sxx = fmaf(pj.w, ex2(ax), sxx);
            // ZZ term: z_i vs z_j
            float az = fmaf(zi2, qj.z, fmaf(zi1, qj.y, zi0 * qj.x));
            szz = fmaf(qj.w, ex2(az), szz);
            // XZ term: x_i vs z_j
            float am = fmaf(xi2, qj.z, fmaf(xi1, qj.y, xi0 * qj.x));
            sxz = fmaf(qj.w, ex2(am), sxz);
        }
        sxx *= pi.w;
        szz *= qi.w;
        sxz *= pi.w;
    }

    // Block reduction (deterministic; no atomics)
    __shared__ float sm0[256], sm1[256], sm2[256];
    int t = threadIdx.x;
    sm0[t] = sxx; sm1[t] = szz; sm2[t] = sxz;
    __syncthreads();
    for (int ofs = 128; ofs > 0; ofs >>= 1) {
        if (t < ofs) {
            sm0[t] += sm0[t + ofs];
            sm1[t] += sm1[t + ofs];
            sm2[t] += sm2[t + ofs];
        }
        __syncthreads();
    }
    if (t == 0) {
        int b = blockIdx.y * gridDim.x + blockIdx.x;
        g_partial[b * 3 + 0] = sm0[0];
        g_partial[b * 3 + 1] = sm1[0];
        g_partial[b * 3 + 2] = sm2[0];
    }
}

__global__ void itl_finalize(const float* __restrict__ ksp,
                             const float* __restrict__ thetap,
                             float* __restrict__ out,
                             int out_size, int N, int nblocks) {
    __shared__ float sm0[256], sm1[256], sm2[256];
    int t = threadIdx.x;
    float a0 = 0.0f, a1 = 0.0f, a2 = 0.0f;
    for (int b = t; b < nblocks; b += 256) {
        a0 += g_partial[b * 3 + 0];
        a1 += g_partial[b * 3 + 1];
        a2 += g_partial[b * 3 + 2];
    }
    sm0[t] = a0; sm1[t] = a1; sm2[t] = a2;
    __syncthreads();
    for (int ofs = 128; ofs > 0; ofs >>= 1) {
        if (t < ofs) {
            sm0[t] += sm0[t + ofs];
            sm1[t] += sm1[t + ofs];
            sm2[t] += sm2[t + ofs];
        }
        __syncthreads();
    }
    if (t == 0) {
        float ks = ksp[0];
        const float TWO_PI = 6.283185307179586f;
        float norm = 1.0f / ((float)N * (float)N * sqrtf(TWO_PI * ks));
        float mxx = sm0[0] * norm;
        float mzz = sm1[0] * norm;
        float mxz = sm2[0] * norm;
        float r = logf(sqrtf(mxx * mzz + 1e-5f) / (mxz + 1e-5f)) * thetap[0];
        out[out_size - 1] = r;
    }
}

__global__ void itl_copy(const float* __restrict__ x,
                         const float* __restrict__ z,
                         float* __restrict__ out,
                         int nx, int nz, int ncopy) {
    int i = blockIdx.x * blockDim.x + threadIdx.x;
    if (i >= ncopy) return;
    out[i] = (i < nx) ? x[i] : z[i - nx];
}

extern "C" void kernel_launch(void* const* d_in, const int* in_sizes, int n_in,
                              void* d_out, int out_size) {
    const float* x     = (const float*)d_in[0];
    const float* z     = (const float*)d_in[1];
    const float* ks    = (const float*)d_in[2];
    const float* theta = (const float*)d_in[3];
    float* out = (float*)d_out;

    int nx = in_sizes[0];
    int nz = in_sizes[1];
    int N = nx / 3;

    // Stage 1: per-point scaled factors
    itl_prep<<<(N + 255) / 256, 256>>>(x, z, ks, N);

    // Stage 2: pairwise sums
    const int JS = 16;
    dim3 grid((N + 255) / 256, JS);
    itl_pairs<<<grid, 256>>>(ks, N, JS);

    // Stage 3: deterministic reduce + scalar
    int nblocks = grid.x * JS;
    itl_finalize<<<1, 256>>>(ks, theta, out, out_size, N, nblocks);

    // Stage 4: pass-through copies of x and z (everything except the scalar slot)
    int ncopy = out_size - 1;
    if (ncopy > 0) {
        int want = nx + nz;
        if (ncopy > want) ncopy = want;
        itl_copy<<<(ncopy + 255) / 256, 256>>>(x, z, out, nx, nz, ncopy);
    }
}

// round 3
// speedup vs baseline: 1.0805x; 1.0805x over previous
#include <cuda_runtime.h>
#include <cuda_bf16.h>

// ITLRegularizer: r = log(sqrt(mxx*mzz+1e-5)/(mxz+1e-5)) * theta
// m** = mean of exp(-d2/ks)/sqrt(2*pi*ks) over N x N pairs, D=3.
//
// Factored: exp(-(|a|^2+|b|^2-2 a.b)/ks) = exp2(s*a.b + c_a + c_b)
// with c = -(log2 e)*|p|^2/ks, s = 2*log2(e)/ks.
// Symmetry: mxx, mzz matrices are symmetric with unit diagonal
// (exp2(2c_i + s|xi|^2) == 1), so full_sum = 2*upper_strict + N.

#define CAP 8192
#define TILE 256
#define NTILES 32      // CAP / TILE
#define XZ_JS 16

__device__ float4 g_px[CAP];            // (x0,x1,x2,c_x)
__device__ float4 g_pz[CAP];            // (z0,z1,z2,c_z)
__device__ float  g_pxx[NTILES * NTILES];
__device__ float  g_pzz[NTILES * NTILES];
__device__ float  g_pxz[NTILES * XZ_JS];

__device__ __forceinline__ float ex2(float a) {
    float r;
    asm("ex2.approx.ftz.f32 %0, %1;" : "=f"(r) : "f"(a));
    return r;
}

// Prep: per-point log-factor c, packed float4 layout, plus the pass-through
// copies of x and z into out (thread i already holds those 6 floats).
__global__ void itl_prep(const float* __restrict__ x,
                         const float* __restrict__ z,
                         const float* __restrict__ ksp,
                         float* __restrict__ out,
                         int N, int nx, int out_size) {
    int i = blockIdx.x * blockDim.x + threadIdx.x;
    if (i >= N) return;
    const float L = 1.4426950408889634f;
    float c = -L / ksp[0];

    float x0 = x[3 * i], x1 = x[3 * i + 1], x2 = x[3 * i + 2];
    float cx = c * (x0 * x0 + x1 * x1 + x2 * x2);
    g_px[i] = make_float4(x0, x1, x2, cx);

    float z0 = z[3 * i], z1 = z[3 * i + 1], z2 = z[3 * i + 2];
    float cz = c * (z0 * z0 + z1 * z1 + z2 * z2);
    g_pz[i] = make_float4(z0, z1, z2, cz);

    // Pass-through (out layout: x, z, ..., scalar at out_size-1)
    int bx = 3 * i;
    if (bx + 2 < out_size - 1) {
        out[bx] = x0; out[bx + 1] = x1; out[bx + 2] = x2;
    }
    int bz = nx + 3 * i;
    if (bz + 2 < out_size - 1) {
        out[bz] = z0; out[bz + 1] = z1; out[bz + 2] = z2;
    }
}

// XX + ZZ over strict upper triangle, tiled 256x256. Block (I=by, J=bx),
// only J >= I does work; J == I uses the j > i predicate.
__global__ void __launch_bounds__(TILE) itl_xxzz(const float* __restrict__ ksp) {
    int I = blockIdx.y, J = blockIdx.x;
    int pid = I * NTILES + J;
    if (J < I) {
        if (threadIdx.x == 0) { g_pxx[pid] = 0.0f; g_pzz[pid] = 0.0f; }
        return;
    }

    const float L = 1.4426950408889634f;
    float s = 2.0f * L / ksp[0];

    int i = I * TILE + threadIdx.x;
    float4 pi = g_px[i];
    float4 qi = g_pz[i];
    float xi0 = pi.x * s, xi1 = pi.y * s, xi2 = pi.z * s;
    float zi0 = qi.x * s, zi1 = qi.y * s, zi2 = qi.z * s;

    float sxx = 0.0f, szz = 0.0f;
    int j0 = J * TILE;

    if (I != J) {
        #pragma unroll 8
        for (int jj = 0; jj < TILE; jj++) {
            int j = j0 + jj;
            float4 pj = g_px[j];
            float4 qj = g_pz[j];
            float ax = fmaf(xi0, pj.x, fmaf(xi1, pj.y, fmaf(xi2, pj.z, pj.w)));
            float az = fmaf(zi0, qj.x, fmaf(zi1, qj.y, fmaf(zi2, qj.z, qj.w)));
            sxx += ex2(ax);
            szz += ex2(az);
        }
    } else {
        #pragma unroll 8
        for (int jj = 0; jj < TILE; jj++) {
            int j = j0 + jj;
            float4 pj = g_px[j];
            float4 qj = g_pz[j];
            float ax = fmaf(xi0, pj.x, fmaf(xi1, pj.y, fmaf(xi2, pj.z, pj.w)));
            float az = fmaf(zi0, qj.x, fmaf(zi1, qj.y, fmaf(zi2, qj.z, qj.w)));
            if (j > i) {
                sxx += ex2(ax);
                szz += ex2(az);
            }
        }
    }
    sxx *= ex2(pi.w);   // b_i factors
    szz *= ex2(qi.w);

    __shared__ float sm0[TILE], sm1[TILE];
    int t = threadIdx.x;
    sm0[t] = sxx; sm1[t] = szz;
    __syncthreads();
    for (int ofs = TILE / 2; ofs > 0; ofs >>= 1) {
        if (t < ofs) { sm0[t] += sm0[t + ofs]; sm1[t] += sm1[t + ofs]; }
        __syncthreads();
    }
    if (t == 0) { g_pxx[pid] = sm0[0]; g_pzz[pid] = sm1[0]; }
}

// XZ: full N x N, i-tiles x j-chunks.
__global__ void __launch_bounds__(TILE) itl_xz(const float* __restrict__ ksp, int N) {
    const float L = 1.4426950408889634f;
    float s = 2.0f * L / ksp[0];

    int i = blockIdx.x * TILE + threadIdx.x;
    int jc = blockIdx.y;
    int span = N / XZ_JS;
    int j0 = jc * span;
    int j1 = j0 + span;

    float4 pi = g_px[i];
    float xi0 = pi.x * s, xi1 = pi.y * s, xi2 = pi.z * s;

    float sxz = 0.0f;
    #pragma unroll 8
    for (int j = j0; j < j1; j++) {
        float4 qj = g_pz[j];
        float a = fmaf(xi0, qj.x, fmaf(xi1, qj.y, fmaf(xi2, qj.z, qj.w)));
        sxz += ex2(a);
    }
    sxz *= ex2(pi.w);

    __shared__ float sm[TILE];
    int t = threadIdx.x;
    sm[t] = sxz;
    __syncthreads();
    for (int ofs = TILE / 2; ofs > 0; ofs >>= 1) {
        if (t < ofs) sm[t] += sm[t + ofs];
        __syncthreads();
    }
    if (t == 0) g_pxz[blockIdx.y * gridDim.x + blockIdx.x] = sm[0];
}

__global__ void itl_finalize(const float* __restrict__ ksp,
                             const float* __restrict__ thetap,
                             float* __restrict__ out,
                             int out_size, int N) {
    __shared__ float sm0[256], sm1[256], sm2[256];
    int t = threadIdx.x;
    float a0 = 0.0f, a1 = 0.0f, a2 = 0.0f;
    for (int b = t; b < NTILES * NTILES; b += 256) {
        a0 += g_pxx[b];
        a1 += g_pzz[b];
    }
    for (int b = t; b < NTILES * XZ_JS; b += 256) {
        a2 += g_pxz[b];
    }
    sm0[t] = a0; sm1[t] = a1; sm2[t] = a2;
    __syncthreads();
    for (int ofs = 128; ofs > 0; ofs >>= 1) {
        if (t < ofs) {
            sm0[t] += sm0[t + ofs];
            sm1[t] += sm1[t + ofs];
            sm2[t] += sm2[t + ofs];
        }
        __syncthreads();
    }
    if (t == 0) {
        float ks = ksp[0];
        const float TWO_PI = 6.283185307179586f;
        float norm = 1.0f / ((float)N * (float)N * sqrtf(TWO_PI * ks));
        float fN = (float)N;
        float mxx = (2.0f * sm0[0] + fN) * norm;   // diag == N exactly
        float mzz = (2.0f * sm1[0] + fN) * norm;
        float mxz = sm2[0] * norm;
        float r = logf(sqrtf(mxx * mzz + 1e-5f) / (mxz + 1e-5f)) * thetap[0];
        out[out_size - 1] = r;
    }
}

extern "C" void kernel_launch(void* const* d_in, const int* in_sizes, int n_in,
                              void* d_out, int out_size) {
    const float* x     = (const float*)d_in[0];
    const float* z     = (const float*)d_in[1];
    const float* ks    = (const float*)d_in[2];
    const float* theta = (const float*)d_in[3];
    float* out = (float*)d_out;

    int nx = in_sizes[0];
    int N = nx / 3;

    itl_prep<<<(N + 255) / 256, 256>>>(x, z, ks, out, N, nx, out_size);

    dim3 gxxzz(NTILES, NTILES);                 // (J, I); J < I early-exit
    itl_xxzz<<<gxxzz, TILE>>>(ks);

    dim3 gxz(N / TILE, XZ_JS);
    itl_xz<<<gxz, TILE>>>(ks, N);

    itl_finalize<<<1, 256>>>(ks, theta, out, out_size, N);
}

// round 4
// speedup vs baseline: 1.1430x; 1.0578x over previous
#include <cuda_runtime.h>
#include <cuda_bf16.h>

// ITLRegularizer: r = log(sqrt(mxx*mzz+1e-5)/(mxz+1e-5)) * theta
// m** = mean of exp(-d2/ks)/sqrt(2*pi*ks) over N x N pairs, D=3.
//
// Factored: exp(-(|a|^2+|b|^2-2 a.b)/ks) = exp2(s*a.b + c_a + c_b)
// with c = -(log2 e)*|p|^2/ks, s = 2*log2(e)/ks.
// mxx/mzz are symmetric with unit diagonal -> full = 2*upper_strict + N.
//
// Single merged pairs kernel: blocks [0,528) = triangle tiles (xx+zz),
// blocks [528,1040) = xz tiles. Last block (atomic ticket) finalizes.

#define CAP 8192
#define TILE 256
#define NT 32                   // CAP / TILE
#define TRI_BLOCKS 528          // NT*(NT+1)/2
#define XZ_JS 16
#define XZ_BLOCKS (NT * XZ_JS)  // 512
#define NBLK (TRI_BLOCKS + XZ_BLOCKS)

__device__ float4 g_px[CAP];    // (x0,x1,x2,c_x)
__device__ float4 g_pz[CAP];    // (z0,z1,z2,c_z)
__device__ float  g_p0[NBLK];   // xx partials
__device__ float  g_p1[NBLK];   // zz partials
__device__ float  g_p2[NBLK];   // xz partials
__device__ unsigned int g_ticket;

__device__ __forceinline__ float ex2(float a) {
    float r;
    asm("ex2.approx.ftz.f32 %0, %1;" : "=f"(r) : "f"(a));
    return r;
}

// Prep: per-point log-factor c, packed float4, pass-through copies, ticket reset.
__global__ void itl_prep(const float* __restrict__ x,
                         const float* __restrict__ z,
                         const float* __restrict__ ksp,
                         float* __restrict__ out,
                         int N, int nx, int out_size) {
    int i = blockIdx.x * blockDim.x + threadIdx.x;
    if (i == 0) g_ticket = 0;
    if (i >= N) return;
    const float L = 1.4426950408889634f;
    float c = -L / ksp[0];

    float x0 = x[3 * i], x1 = x[3 * i + 1], x2 = x[3 * i + 2];
    g_px[i] = make_float4(x0, x1, x2, c * (x0 * x0 + x1 * x1 + x2 * x2));

    float z0 = z[3 * i], z1 = z[3 * i + 1], z2 = z[3 * i + 2];
    g_pz[i] = make_float4(z0, z1, z2, c * (z0 * z0 + z1 * z1 + z2 * z2));

    int bx = 3 * i;
    if (bx + 2 < out_size - 1) { out[bx] = x0; out[bx + 1] = x1; out[bx + 2] = x2; }
    int bz = nx + 3 * i;
    if (bz + 2 < out_size - 1) { out[bz] = z0; out[bz + 1] = z1; out[bz + 2] = z2; }
}

__global__ void __launch_bounds__(TILE) itl_pairs(const float* __restrict__ ksp,
                                                  const float* __restrict__ thetap,
                                                  float* __restrict__ out,
                                                  int out_size, int N) {
    const float L = 1.4426950408889634f;
    float s = 2.0f * L / ksp[0];

    int blk = blockIdx.x;
    int t = threadIdx.x;

    float v0 = 0.0f, v1 = 0.0f, v2 = 0.0f;  // xx, zz, xz contributions

    if (blk < TRI_BLOCKS) {
        // ---- Triangle tile: map linear -> (I, J), J >= I ----
        int rem = blk, I = 0;
        while (rem >= NT - I) { rem -= NT - I; I++; }
        int J = I + rem;

        int i = I * TILE + t;
        float4 pi = g_px[i];
        float4 qi = g_pz[i];
        float xi0 = pi.x * s, xi1 = pi.y * s, xi2 = pi.z * s;
        float zi0 = qi.x * s, zi1 = qi.y * s, zi2 = qi.z * s;

        int j0 = J * TILE;
        if (I != J) {
            #pragma unroll 8
            for (int jj = 0; jj < TILE; jj++) {
                int j = j0 + jj;
                float4 pj = g_px[j];
                float4 qj = g_pz[j];
                float ax = fmaf(xi0, pj.x, fmaf(xi1, pj.y, fmaf(xi2, pj.z, pj.w)));
                float az = fmaf(zi0, qj.x, fmaf(zi1, qj.y, fmaf(zi2, qj.z, qj.w)));
                v0 += ex2(ax);
                v1 += ex2(az);
            }
        } else {
            #pragma unroll 8
            for (int jj = 0; jj < TILE; jj++) {
                int j = j0 + jj;
                float4 pj = g_px[j];
                float4 qj = g_pz[j];
                float ax = fmaf(xi0, pj.x, fmaf(xi1, pj.y, fmaf(xi2, pj.z, pj.w)));
                float az = fmaf(zi0, qj.x, fmaf(zi1, qj.y, fmaf(zi2, qj.z, qj.w)));
                if (j > i) { v0 += ex2(ax); v1 += ex2(az); }
            }
        }
        v0 *= ex2(pi.w);
        v1 *= ex2(qi.w);
    } else {
        // ---- XZ tile: full rectangle ----
        int idx = blk - TRI_BLOCKS;
        int it = idx % NT;          // i-tile
        int jc = idx / NT;          // j-chunk
        int i = it * TILE + t;
        int span = N / XZ_JS;
        int j0 = jc * span, j1 = j0 + span;

        float4 pi = g_px[i];
        float xi0 = pi.x * s, xi1 = pi.y * s, xi2 = pi.z * s;

        #pragma unroll 8
        for (int j = j0; j < j1; j++) {
            float4 qj = g_pz[j];
            float a = fmaf(xi0, qj.x, fmaf(xi1, qj.y, fmaf(xi2, qj.z, qj.w)));
            v2 += ex2(a);
        }
        v2 *= ex2(pi.w);
    }

    // ---- Block reduction ----
    __shared__ float sm0[TILE], sm1[TILE], sm2[TILE];
    sm0[t] = v0; sm1[t] = v1; sm2[t] = v2;
    __syncthreads();
    for (int ofs = TILE / 2; ofs > 0; ofs >>= 1) {
        if (t < ofs) {
            sm0[t] += sm0[t + ofs];
            sm1[t] += sm1[t + ofs];
            sm2[t] += sm2[t + ofs];
        }
        __syncthreads();
    }

    __shared__ bool is_last;
    if (t == 0) {
        g_p0[blk] = sm0[0];
        g_p1[blk] = sm1[0];
        g_p2[blk] = sm2[0];
        __threadfence();
        unsigned int prev = atomicAdd(&g_ticket, 1u);
        is_last = (prev == (unsigned int)(NBLK - 1));
    }
    __syncthreads();

    // ---- Last block: deterministic final reduce + scalar ----
    if (is_last) {
        float a0 = 0.0f, a1 = 0.0f, a2 = 0.0f;
        for (int b = t; b < NBLK; b += TILE) {
            a0 += g_p0[b];
            a1 += g_p1[b];
            a2 += g_p2[b];
        }
        sm0[t] = a0; sm1[t] = a1; sm2[t] = a2;
        __syncthreads();
        for (int ofs = TILE / 2; ofs > 0; ofs >>= 1) {
            if (t < ofs) {
                sm0[t] += sm0[t + ofs];
                sm1[t] += sm1[t + ofs];
                sm2[t] += sm2[t + ofs];
            }
            __syncthreads();
        }
        if (t == 0) {
            float ks = ksp[0];
            const float TWO_PI = 6.283185307179586f;
            float norm = 1.0f / ((float)N * (float)N * sqrtf(TWO_PI * ks));
            float fN = (float)N;
            float mxx = (2.0f * sm0[0] + fN) * norm;   // diag == N exactly
            float mzz = (2.0f * sm1[0] + fN) * norm;
            float mxz = sm2[0] * norm;
            float r = logf(sqrtf(mxx * mzz + 1e-5f) / (mxz + 1e-5f)) * thetap[0];
            out[out_size - 1] = r;
        }
    }
}

extern "C" void kernel_launch(void* const* d_in, const int* in_sizes, int n_in,
                              void* d_out, int out_size) {
    const float* x     = (const float*)d_in[0];
    const float* z     = (const float*)d_in[1];
    const float* ks    = (const float*)d_in[2];
    const float* theta = (const float*)d_in[3];
    float* out = (float*)d_out;

    int nx = in_sizes[0];
    int N = nx / 3;

    itl_prep<<<(N + 255) / 256, 256>>>(x, z, ks, out, N, nx, out_size);
    itl_pairs<<<NBLK, TILE>>>(ks, theta, out, out_size, N);
}

// round 6
// speedup vs baseline: 2.2792x; 1.9941x over previous
#include <cuda_runtime.h>
#include <cuda_bf16.h>

// ITLRegularizer: r = log(sqrt(mxx*mzz+1e-5)/(mxz+1e-5)) * theta
// m** = mean of exp(-d2/ks)/sqrt(2*pi*ks) over N x N pairs, D=3.
//
// Factored: exp(-(|a|^2+|b|^2-2 a.b)/ks) = exp2(s*a.b + c_a + c_b),
// c = -(log2 e)*|p|^2/ks, s = 2*log2(e)/ks.
// mxx/mzz symmetric, unit diagonal -> full = 2*upper_strict + N.
//
// Inner loops are packed f32x2: the xx & zz chains share j-loads lane-for-lane
// (triangle path); the xz path pairs consecutive j's via a transposed layout.
// j-tiles staged in shared memory (LDS broadcast) to get off the L1tex
// global-wavefront path.

#define CAP 8192
#define TILE 256
#define NT 32                   // CAP / TILE
#define TRI_BLOCKS 528          // NT*(NT+1)/2
#define XZ_JS 16
#define XZ_BLOCKS (NT * XZ_JS)  // 512
#define NBLK (TRI_BLOCKS + XZ_BLOCKS)

__device__ float4 g_A[CAP];       // (x0, z0, x1, z1)
__device__ float4 g_B[CAP];       // (x2, z2, cx, cz)
__device__ float4 g_ZA[CAP / 2];  // (z0_even, z0_odd, z1_even, z1_odd)
__device__ float4 g_ZB[CAP / 2];  // (z2_even, z2_odd, cz_even, cz_odd)
__device__ float  g_p0[NBLK];
__device__ float  g_p1[NBLK];
__device__ float  g_p2[NBLK];
__device__ unsigned int g_ticket;

__device__ __forceinline__ float ex2(float a) {
    float r;
    asm("ex2.approx.ftz.f32 %0, %1;" : "=f"(r) : "f"(a));
    return r;
}
__device__ __forceinline__ unsigned long long pk2(float lo, float hi) {
    unsigned long long r;
    asm("mov.b64 %0, {%1, %2};" : "=l"(r) : "f"(lo), "f"(hi));
    return r;
}
__device__ __forceinline__ void upk2(float& lo, float& hi, unsigned long long v) {
    asm("mov.b64 {%0, %1}, %2;" : "=f"(lo), "=f"(hi) : "l"(v));
}
__device__ __forceinline__ unsigned long long fma2(unsigned long long a,
                                                   unsigned long long b,
                                                   unsigned long long c) {
    unsigned long long d;
    asm("fma.rn.f32x2 %0, %1, %2, %3;" : "=l"(d) : "l"(a), "l"(b), "l"(c));
    return d;
}

// Prep: packed layouts, per-point log-factors, pass-through copies, ticket reset.
__global__ void itl_prep(const float* __restrict__ x,
                         const float* __restrict__ z,
                         const float* __restrict__ ksp,
                         float* __restrict__ out,
                         int N, int nx, int out_size) {
    int i = blockIdx.x * blockDim.x + threadIdx.x;
    if (i == 0) g_ticket = 0;
    if (i >= N) return;
    const float L = 1.4426950408889634f;
    float c = -L / ksp[0];

    float x0 = x[3 * i], x1 = x[3 * i + 1], x2 = x[3 * i + 2];
    float z0 = z[3 * i], z1 = z[3 * i + 1], z2 = z[3 * i + 2];
    float cx = c * (x0 * x0 + x1 * x1 + x2 * x2);
    float cz = c * (z0 * z0 + z1 * z1 + z2 * z2);

    g_A[i] = make_float4(x0, z0, x1, z1);
    g_B[i] = make_float4(x2, z2, cx, cz);

    // Transposed pair layout for the xz path.
    int p = i >> 1, o = i & 1;
    float* ZA = (float*)g_ZA;
    float* ZB = (float*)g_ZB;
    ZA[4 * p + o]     = z0;
    ZA[4 * p + 2 + o] = z1;
    ZB[4 * p + o]     = z2;
    ZB[4 * p + 2 + o] = cz;

    int bx = 3 * i;
    if (bx + 2 < out_size - 1) { out[bx] = x0; out[bx + 1] = x1; out[bx + 2] = x2; }
    int bz = nx + 3 * i;
    if (bz + 2 < out_size - 1) { out[bz] = z0; out[bz + 1] = z1; out[bz + 2] = z2; }
}

__global__ void __launch_bounds__(TILE) itl_pairs(const float* __restrict__ ksp,
                                                  const float* __restrict__ thetap,
                                                  float* __restrict__ out,
                                                  int out_size, int N) {
    const float L = 1.4426950408889634f;
    float s = 2.0f * L / ksp[0];

    int blk = blockIdx.x;
    int t = threadIdx.x;

    __shared__ float4 smA[TILE];   // 4KB
    __shared__ float4 smB[TILE];   // 4KB
    __shared__ float sm0[TILE], sm1[TILE], sm2[TILE];

    float v0 = 0.0f, v1 = 0.0f, v2 = 0.0f;

    if (blk < TRI_BLOCKS) {
        // ---- Triangle tile (xx + zz), linear -> (I, J), J >= I ----
        int rem = blk, I = 0;
        while (rem >= NT - I) { rem -= NT - I; I++; }
        int J = I + rem;
        int i = I * TILE + t;
        int j0 = J * TILE;

        // Stage J-tile into smem.
        smA[t] = g_A[j0 + t];
        smB[t] = g_B[j0 + t];
        __syncthreads();

        float4 Ai = g_A[i];
        float4 Bi = g_B[i];
        unsigned long long u0 = pk2(Ai.x * s, Ai.y * s);
        unsigned long long u1 = pk2(Ai.z * s, Ai.w * s);
        unsigned long long u2 = pk2(Bi.x * s, Bi.y * s);

        if (I != J) {
            #pragma unroll 8
            for (int jj = 0; jj < TILE; jj++) {
                ulonglong2 a = *reinterpret_cast<const ulonglong2*>(&smA[jj]);
                ulonglong2 b = *reinterpret_cast<const ulonglong2*>(&smB[jj]);
                unsigned long long d = fma2(u0, a.x, fma2(u1, a.y, fma2(u2, b.x, b.y)));
                float lo, hi; upk2(lo, hi, d);
                v0 += ex2(lo);
                v1 += ex2(hi);
            }
        } else {
            #pragma unroll 8
            for (int jj = 0; jj < TILE; jj++) {
                ulonglong2 a = *reinterpret_cast<const ulonglong2*>(&smA[jj]);
                ulonglong2 b = *reinterpret_cast<const ulonglong2*>(&smB[jj]);
                unsigned long long d = fma2(u0, a.x, fma2(u1, a.y, fma2(u2, b.x, b.y)));
                float lo, hi; upk2(lo, hi, d);
                if (j0 + jj > i) { v0 += ex2(lo); v1 += ex2(hi); }
            }
        }
        v0 *= ex2(Bi.z);   // b_i factors
        v1 *= ex2(Bi.w);
    } else {
        // ---- XZ tile: x_i against a 512-wide z chunk, 2 j's per step ----
        int idx = blk - TRI_BLOCKS;
        int it = idx % NT;
        int jc = idx / NT;
        int i = it * TILE + t;
        int p0 = jc * TILE;        // pair index base (span = 512 j = 256 pairs)

        smA[t] = g_ZA[p0 + t];
        smB[t] = g_ZB[p0 + t];
        __syncthreads();

        float4 Ai = g_A[i];
        float4 Bi = g_B[i];
        float xi0 = Ai.x * s, xi1 = Ai.z * s, xi2 = Bi.x * s;
        unsigned long long w0 = pk2(xi0, xi0);
        unsigned long long w1 = pk2(xi1, xi1);
        unsigned long long w2 = pk2(xi2, xi2);

        #pragma unroll 8
        for (int pp = 0; pp < TILE; pp++) {
            ulonglong2 a = *reinterpret_cast<const ulonglong2*>(&smA[pp]);
            ulonglong2 b = *reinterpret_cast<const ulonglong2*>(&smB[pp]);
            unsigned long long d = fma2(w0, a.x, fma2(w1, a.y, fma2(w2, b.x, b.y)));
            float lo, hi; upk2(lo, hi, d);
            v2 += ex2(lo);
            v2 += ex2(hi);
        }
        v2 *= ex2(Bi.z);   // b_i for the x point
    }

    // ---- Block reduction ----
    __syncthreads();
    sm0[t] = v0; sm1[t] = v1; sm2[t] = v2;
    __syncthreads();
    for (int ofs = TILE / 2; ofs > 0; ofs >>= 1) {
        if (t < ofs) {
            sm0[t] += sm0[t + ofs];
            sm1[t] += sm1[t + ofs];
            sm2[t] += sm2[t + ofs];
        }
        __syncthreads();
    }

    __shared__ bool is_last;
    if (t == 0) {
        g_p0[blk] = sm0[0];
        g_p1[blk] = sm1[0];
        g_p2[blk] = sm2[0];
        __threadfence();
        unsigned int prev = atomicAdd(&g_ticket, 1u);
        is_last = (prev == (unsigned int)(NBLK - 1));
    }
    __syncthreads();

    // ---- Last block: deterministic final reduce + scalar ----
    if (is_last) {
        float a0 = 0.0f, a1 = 0.0f, a2 = 0.0f;
        for (int b = t; b < NBLK; b += TILE) {
            a0 += g_p0[b];
            a1 += g_p1[b];
            a2 += g_p2[b];
        }
        sm0[t] = a0; sm1[t] = a1; sm2[t] = a2;
        __syncthreads();
        for (int ofs = TILE / 2; ofs > 0; ofs >>= 1) {
            if (t < ofs) {
                sm0[t] += sm0[t + ofs];
                sm1[t] += sm1[t + ofs];
                sm2[t] += sm2[t + ofs];
            }
            __syncthreads();
        }
        if (t == 0) {
            float ks = ksp[0];
            const float TWO_PI = 6.283185307179586f;
            float norm = 1.0f / ((float)N * (float)N * sqrtf(TWO_PI * ks));
            float fN = (float)N;
            float mxx = (2.0f * sm0[0] + fN) * norm;   // diag == N exactly
            float mzz = (2.0f * sm1[0] + fN) * norm;
            float mxz = sm2[0] * norm;
            float r = logf(sqrtf(mxx * mzz + 1e-5f) / (mxz + 1e-5f)) * thetap[0];
            out[out_size - 1] = r;
        }
    }
}

extern "C" void kernel_launch(void* const* d_in, const int* in_sizes, int n_in,
                              void* d_out, int out_size) {
    const float* x     = (const float*)d_in[0];
    const float* z     = (const float*)d_in[1];
    const float* ks    = (const float*)d_in[2];
    const float* theta = (const float*)d_in[3];
    float* out = (float*)d_out;

    int nx = in_sizes[0];
    int N = nx / 3;

    itl_prep<<<(N + 255) / 256, 256>>>(x, z, ks, out, N, nx, out_size);
    itl_pairs<<<NBLK, TILE>>>(ks, theta, out, out_size, N);
}